// round 4
// baseline (speedup 1.0000x reference)
#include <cuda_runtime.h>

#define BS   8192
#define DIM  4096
#define BLK  64
#define NB   64
#define HID  128
#define ROWS_PER_CTA 128

// ---- scratch (device globals: no allocations allowed) ----
__device__ float g_bufA[(size_t)BS * DIM];
__device__ float g_bufB[(size_t)BS * DIM];

// ---- shared memory layout (floats) ----
#define AS_LD 68                       // 64 + pad (keeps fp32x4 alignment, dodges bank conflicts)
#define HS_LD 132                      // 128 + pad
#define OFF_AS 0
#define SZ_AS  (128 * AS_LD)           // 8704
#define OFF_W1 (OFF_AS + SZ_AS)
#define SZ_W1  (64 * 128)              // 8192
#define OFF_W2 (OFF_W1 + SZ_W1)
#define SZ_W2  (128 * 64)              // 8192
#define OFF_HS (OFF_W2 + SZ_W2)
#define SZ_HS  (128 * HS_LD)           // 16896
#define OFF_B1 (OFF_HS + SZ_HS)
#define OFF_B2 (OFF_B1 + 128)
#define SMEM_FLOATS (OFF_B2 + 64)      // 42176 floats
#define SMEM_BYTES  (SMEM_FLOATS * 4)  // 168704 bytes

// One CTA: block n (64 in/out features), 128 rows.
//   H = ELU(A @ W1 + b1)  [128 x 128]
//   O = H @ W2 + b2 + A   [128 x 64]
__global__ __launch_bounds__(256, 1)
void mlp_block_kernel(const float* __restrict__ act_in,
                      float* __restrict__ act_out,
                      const float* __restrict__ w1,
                      const float* __restrict__ b1,
                      const float* __restrict__ w2,
                      const float* __restrict__ b2)
{
    extern __shared__ float s[];
    float* As  = s + OFF_AS;
    float* W1s = s + OFF_W1;
    float* W2s = s + OFF_W2;
    float* Hs  = s + OFF_HS;
    float* b1s = s + OFF_B1;
    float* b2s = s + OFF_B2;

    const int tid = threadIdx.x;
    const int m = blockIdx.x;           // row tile
    const int n = blockIdx.y;           // feature block
    const size_t row0 = (size_t)m * ROWS_PER_CTA;

    // ---- load A tile (128 x 64) coalesced ----
    {
        const float* src = act_in + row0 * DIM + (size_t)n * BLK;
        for (int idx = tid; idx < 128 * 16; idx += 256) {
            int rr = idx >> 4, c4 = idx & 15;
            float4 v = *reinterpret_cast<const float4*>(src + (size_t)rr * DIM + c4 * 4);
            *reinterpret_cast<float4*>(As + rr * AS_LD + c4 * 4) = v;
        }
    }
    // ---- load weights / biases ----
    {
        const float4* s1 = reinterpret_cast<const float4*>(w1 + (size_t)n * (BLK * HID));
        const float4* s2 = reinterpret_cast<const float4*>(w2 + (size_t)n * (HID * BLK));
        float4* d1 = reinterpret_cast<float4*>(W1s);
        float4* d2 = reinterpret_cast<float4*>(W2s);
        for (int idx = tid; idx < 2048; idx += 256) { d1[idx] = s1[idx]; d2[idx] = s2[idx]; }
        if (tid < 128) b1s[tid] = b1[(size_t)n * HID + tid];
        if (tid < 64)  b2s[tid] = b2[(size_t)n * BLK + tid];
    }
    __syncthreads();

    const int tx = tid & 15, ty = tid >> 4;
    int r[8];
#pragma unroll
    for (int i = 0; i < 4; i++) { r[i] = ty * 4 + i; r[i + 4] = 64 + ty * 4 + i; }

    // ================= GEMM1: H = A @ W1 =================
    float acc[8][8];
#pragma unroll
    for (int i = 0; i < 8; i++)
#pragma unroll
        for (int j = 0; j < 8; j++) acc[i][j] = 0.f;

#pragma unroll 4
    for (int k = 0; k < BLK; k += 4) {
        float4 av[8];
#pragma unroll
        for (int i = 0; i < 8; i++)
            av[i] = *reinterpret_cast<const float4*>(As + r[i] * AS_LD + k);
#pragma unroll
        for (int kk = 0; kk < 4; kk++) {
            float4 bv0 = *reinterpret_cast<const float4*>(W1s + (k + kk) * HID + tx * 4);
            float4 bv1 = *reinterpret_cast<const float4*>(W1s + (k + kk) * HID + 64 + tx * 4);
            float bb[8] = {bv0.x, bv0.y, bv0.z, bv0.w, bv1.x, bv1.y, bv1.z, bv1.w};
#pragma unroll
            for (int i = 0; i < 8; i++) {
                float a = (kk == 0) ? av[i].x : (kk == 1) ? av[i].y : (kk == 2) ? av[i].z : av[i].w;
#pragma unroll
                for (int j = 0; j < 8; j++) acc[i][j] += a * bb[j];
            }
        }
    }

    // ---- epilogue 1: bias + ELU -> Hs ----
#pragma unroll
    for (int i = 0; i < 8; i++) {
#pragma unroll
        for (int jg = 0; jg < 2; jg++) {
            float4 v;
            float* pv = &v.x;
#pragma unroll
            for (int j = 0; j < 4; j++) {
                int c = jg * 64 + tx * 4 + j;
                float h = acc[i][jg * 4 + j] + b1s[c];
                pv[j] = (h > 0.f) ? h : (__expf(h) - 1.f);
            }
            *reinterpret_cast<float4*>(Hs + r[i] * HS_LD + jg * 64 + tx * 4) = v;
        }
    }
    __syncthreads();

    // ================= GEMM2: O = H @ W2 + b2 + A =================
    float acc2[8][4];
#pragma unroll
    for (int i = 0; i < 8; i++)
#pragma unroll
        for (int j = 0; j < 4; j++) acc2[i][j] = 0.f;

#pragma unroll 4
    for (int k = 0; k < HID; k += 4) {
        float4 av[8];
#pragma unroll
        for (int i = 0; i < 8; i++)
            av[i] = *reinterpret_cast<const float4*>(Hs + r[i] * HS_LD + k);
#pragma unroll
        for (int kk = 0; kk < 4; kk++) {
            float4 bv = *reinterpret_cast<const float4*>(W2s + (k + kk) * BLK + tx * 4);
            float bb[4] = {bv.x, bv.y, bv.z, bv.w};
#pragma unroll
            for (int i = 0; i < 8; i++) {
                float a = (kk == 0) ? av[i].x : (kk == 1) ? av[i].y : (kk == 2) ? av[i].z : av[i].w;
#pragma unroll
                for (int j = 0; j < 4; j++) acc2[i][j] += a * bb[j];
            }
        }
    }

    float* dst = act_out + row0 * DIM + (size_t)n * BLK;
#pragma unroll
    for (int i = 0; i < 8; i++) {
        float4 res = *reinterpret_cast<const float4*>(As + r[i] * AS_LD + tx * 4);
        float4 o;
        o.x = acc2[i][0] + b2s[tx * 4 + 0] + res.x;
        o.y = acc2[i][1] + b2s[tx * 4 + 1] + res.y;
        o.z = acc2[i][2] + b2s[tx * 4 + 2] + res.z;
        o.w = acc2[i][3] + b2s[tx * 4 + 3] + res.w;
        *reinterpret_cast<float4*>(dst + (size_t)r[i] * DIM + tx * 4) = o;
    }
}

// Per-row 64x64 transpose: out[row, b*64+a] = in[row, a*64+b]   (involution)
__global__ __launch_bounds__(256)
void transpose64_kernel(const float* __restrict__ in, float* __restrict__ out)
{
    __shared__ float s[64 * 65];
    const size_t base = (size_t)blockIdx.x * DIM;
    for (int idx = threadIdx.x; idx < DIM; idx += 256) {
        int a = idx >> 6, b = idx & 63;
        s[a * 65 + b] = in[base + idx];
    }
    __syncthreads();
    for (int idx = threadIdx.x; idx < DIM; idx += 256) {
        int b = idx >> 6, a = idx & 63;          // out flat = b*64 + a
        out[base + idx] = s[a * 65 + b];
    }
}

static float* symbol_addr(const void* sym)
{
    void* p = nullptr;
    cudaGetSymbolAddress(&p, sym);
    return (float*)p;
}

extern "C" void kernel_launch(void* const* d_in, const int* in_sizes, int n_in,
                              void* d_out, int out_size)
{
    (void)in_sizes; (void)n_in; (void)out_size;
    const float* x  = (const float*)d_in[0];
    const float* w1 = (const float*)d_in[1];
    const float* b1 = (const float*)d_in[2];
    const float* w2 = (const float*)d_in[3];
    const float* b2 = (const float*)d_in[4];
    float* out = (float*)d_out;

    float* bufA = symbol_addr(g_bufA);
    float* bufB = symbol_addr(g_bufB);

    cudaFuncSetAttribute((const void*)mlp_block_kernel,
                         cudaFuncAttributeMaxDynamicSharedMemorySize, SMEM_BYTES);

    const dim3 grid(BS / ROWS_PER_CTA, NB);

    // layer 0 (gap=1 shuffle is identity): x -> bufA
    mlp_block_kernel<<<grid, 256, SMEM_BYTES>>>(x, bufA, w1, b1, w2, b2);
    // gap=64 shuffle: per-row 64x64 transpose
    transpose64_kernel<<<BS, 256>>>(bufA, bufB);
    // layer 1: bufB -> bufA
    const size_t o1  = (size_t)NB * BLK * HID;
    const size_t ob1 = (size_t)NB * HID;
    const size_t o2  = (size_t)NB * HID * BLK;
    const size_t ob2 = (size_t)NB * BLK;
    mlp_block_kernel<<<grid, 256, SMEM_BYTES>>>(bufB, bufA, w1 + o1, b1 + ob1, w2 + o2, b2 + ob2);
    // inverse shuffle (same transpose): bufA -> out
    transpose64_kernel<<<BS, 256>>>(bufA, out);
}

// round 7
// speedup vs baseline: 1.0322x; 1.0322x over previous
#include <cuda_runtime.h>
#include <cuda_bf16.h>
#include <cstdint>

#define BS   8192
#define DIM  4096
#define BLK  64
#define NB   64
#define HID  128

// ================= device scratch (no allocs allowed) =================
__device__ float g_bufA[(size_t)BS * DIM];
__device__ float g_bufB[(size_t)BS * DIM];
// prepped bf16 hi/lo weights, dense k-contiguous:
//   W1^T: [t][e=128][d=64]   W2^T: [t][o=64][e=128]     (t = layer*64 + n)
__device__ __nv_bfloat16 g_w1t_hi[2 * 64 * 8192];
__device__ __nv_bfloat16 g_w1t_lo[2 * 64 * 8192];
__device__ __nv_bfloat16 g_w2t_hi[2 * 64 * 8192];
__device__ __nv_bfloat16 g_w2t_lo[2 * 64 * 8192];

// ================= smem layout (bytes) =================
// A fp32:   128 x 68 f32                     [0, 34816)
// A bf16:   hi/lo 128 x 72 bf16              [34816, 71680)   (dead after GEMM1)
// W1^T:     hi/lo 128 x 72 bf16              [71680, 108544)  (dead after GEMM1)
// H bf16:   hi/lo 128 x 136 bf16  OVERLAYS A-bf16/W1 region [34816, 104448)
// W2^T:     hi/lo  64 x 136 bf16             [108544, 143360)
// b1 (128 f32), b2 (64 f32)                  [143360, 144128)
#define SB_ASF32  0
#define SB_AHI    34816
#define SB_ALO    53248
#define SB_W1HI   71680
#define SB_W1LO   90112
#define SB_HHI    34816
#define SB_HLO    69632
#define SB_W2HI   108544
#define SB_W2LO   125952
#define SB_B1     143360
#define SB_B2     143872
#define SMEM_TOTAL 144128

#define LDA 72    // bf16 stride for A / W1^T tiles (conflict-free: (4g+t)%32 distinct)
#define LDH 136   // bf16 stride for H / W2^T tiles

__device__ __forceinline__ uint32_t pack_bf(float a, float b) {
    uint32_t lo = (uint32_t)__bfloat16_as_ushort(__float2bfloat16(a));
    uint32_t hi = (uint32_t)__bfloat16_as_ushort(__float2bfloat16(b));
    return (hi << 16) | lo;
}

// D = A(16x16,row) * B(16x8,col) + D ; bf16 in, f32 accum
__device__ __forceinline__ void mma16816(float* c, uint32_t a0, uint32_t a1,
                                         uint32_t a2, uint32_t a3,
                                         uint32_t b0, uint32_t b1) {
    asm("mma.sync.aligned.m16n8k16.row.col.f32.bf16.bf16.f32 "
        "{%0,%1,%2,%3}, {%4,%5,%6,%7}, {%8,%9}, {%0,%1,%2,%3};"
        : "+f"(c[0]), "+f"(c[1]), "+f"(c[2]), "+f"(c[3])
        : "r"(a0), "r"(a1), "r"(a2), "r"(a3), "r"(b0), "r"(b1));
}

// ============== weight prep: fp32 -> transposed bf16 hi/lo ==============
__global__ void prep_weights(const float* __restrict__ w1, const float* __restrict__ w2)
{
    size_t idx = (size_t)blockIdx.x * blockDim.x + threadIdx.x;
    const size_t HALF = (size_t)2 * 64 * 64 * 128;   // 1,048,576
    if (idx < HALF) {
        // w1: [t][d][e] -> W1^T [t][e][d]
        int e = idx & 127, d = (idx >> 7) & 63;
        size_t t = idx >> 13;
        float v = w1[idx];
        __nv_bfloat16 h = __float2bfloat16(v);
        g_w1t_hi[t * 8192 + e * 64 + d] = h;
        g_w1t_lo[t * 8192 + e * 64 + d] = __float2bfloat16(v - __bfloat162float(h));
    } else if (idx < 2 * HALF) {
        // w2: [t][e][o] -> W2^T [t][o][e]
        size_t i2 = idx - HALF;
        int o = i2 & 63, e = (i2 >> 6) & 127;
        size_t t = i2 >> 13;
        float v = w2[i2];
        __nv_bfloat16 h = __float2bfloat16(v);
        g_w2t_hi[t * 8192 + o * 128 + e] = h;
        g_w2t_lo[t * 8192 + o * 128 + e] = __float2bfloat16(v - __bfloat162float(h));
    }
}

// ============== fused block MLP on HMMA tensor cores ==============
__global__ __launch_bounds__(256, 1)
void mlp_tc_kernel(const float* __restrict__ act_in, float* __restrict__ act_out,
                   int layer, const float* __restrict__ b1g, const float* __restrict__ b2g)
{
    extern __shared__ unsigned char smem[];
    float* As  = (float*)(smem + SB_ASF32);
    float* b1s = (float*)(smem + SB_B1);
    float* b2s = (float*)(smem + SB_B2);

    const int tid = threadIdx.x;
    const int m = blockIdx.x, n = blockIdx.y;
    const size_t t = (size_t)layer * 64 + n;
    const size_t row0 = (size_t)m * 128;

    // ---- load A tile (128x64 fp32, coalesced) ----
    {
        const float* src = act_in + row0 * DIM + (size_t)n * BLK;
        for (int idx = tid; idx < 2048; idx += 256) {
            int rr = idx >> 4, c4 = idx & 15;
            float4 v = *reinterpret_cast<const float4*>(src + (size_t)rr * DIM + c4 * 4);
            *reinterpret_cast<float4*>(As + rr * 68 + c4 * 4) = v;
        }
    }
    // ---- copy weights into padded smem tiles (u32 granularity) ----
    {
        const uint32_t* s1h = (const uint32_t*)(g_w1t_hi + t * 8192);
        const uint32_t* s1l = (const uint32_t*)(g_w1t_lo + t * 8192);
        const uint32_t* s2h = (const uint32_t*)(g_w2t_hi + t * 8192);
        const uint32_t* s2l = (const uint32_t*)(g_w2t_lo + t * 8192);
        for (int i = tid; i < 4096; i += 256) {
            int e = i >> 5, p = i & 31;                       // W1^T row e, bf16-pair p
            uint32_t doff = (uint32_t)(e * LDA + p * 2) * 2;  // bytes
            *(uint32_t*)(smem + SB_W1HI + doff) = s1h[i];
            *(uint32_t*)(smem + SB_W1LO + doff) = s1l[i];
            int o = i >> 6, q = i & 63;                       // W2^T row o, pair q
            uint32_t doff2 = (uint32_t)(o * LDH + q * 2) * 2;
            *(uint32_t*)(smem + SB_W2HI + doff2) = s2h[i];
            *(uint32_t*)(smem + SB_W2LO + doff2) = s2l[i];
        }
        if (tid < 128)      b1s[tid] = b1g[(size_t)n * HID + tid];
        else if (tid < 192) b2s[tid - 128] = b2g[(size_t)n * BLK + (tid - 128)];
    }
    __syncthreads();

    // ---- convert A -> bf16 hi/lo tiles ----
    {
        const int rr = tid & 127, hf = tid >> 7;
#pragma unroll
        for (int j = 0; j < 16; j++) {
            int c = hf * 32 + 2 * j;
            float v0 = As[rr * 68 + c], v1 = As[rr * 68 + c + 1];
            float h0 = __bfloat162float(__float2bfloat16(v0));
            float h1 = __bfloat162float(__float2bfloat16(v1));
            uint32_t off = (uint32_t)(rr * LDA + c) * 2;
            *(uint32_t*)(smem + SB_AHI + off) = pack_bf(h0, h1);
            *(uint32_t*)(smem + SB_ALO + off) = pack_bf(v0 - h0, v1 - h1);
        }
    }
    __syncthreads();

    const int w = tid >> 5, lane = tid & 31;
    const int g = lane >> 2, tg = lane & 3;
    const int row = w * 16 + g;          // this thread's fragment rows: row, row+8

    // ================= GEMM1: H(128x128) = split(A) @ split(W1^T) =================
    float acc[16][4];
#pragma unroll
    for (int i = 0; i < 16; i++) { acc[i][0] = acc[i][1] = acc[i][2] = acc[i][3] = 0.f; }

#pragma unroll
    for (int kt = 0; kt < 4; kt++) {
        const uint32_t ka = (uint32_t)(kt * 16 + 2 * tg) * 2;  // byte offset along k
        uint32_t ah0 = *(uint32_t*)(smem + SB_AHI + (uint32_t)row * (LDA * 2) + ka);
        uint32_t ah1 = *(uint32_t*)(smem + SB_AHI + (uint32_t)(row + 8) * (LDA * 2) + ka);
        uint32_t ah2 = *(uint32_t*)(smem + SB_AHI + (uint32_t)row * (LDA * 2) + ka + 16);
        uint32_t ah3 = *(uint32_t*)(smem + SB_AHI + (uint32_t)(row + 8) * (LDA * 2) + ka + 16);
        uint32_t al0 = *(uint32_t*)(smem + SB_ALO + (uint32_t)row * (LDA * 2) + ka);
        uint32_t al1 = *(uint32_t*)(smem + SB_ALO + (uint32_t)(row + 8) * (LDA * 2) + ka);
        uint32_t al2 = *(uint32_t*)(smem + SB_ALO + (uint32_t)row * (LDA * 2) + ka + 16);
        uint32_t al3 = *(uint32_t*)(smem + SB_ALO + (uint32_t)(row + 8) * (LDA * 2) + ka + 16);
#pragma unroll
        for (int nt = 0; nt < 16; nt++) {
            const uint32_t e = (uint32_t)(nt * 8 + g);
            uint32_t bh0 = *(uint32_t*)(smem + SB_W1HI + e * (LDA * 2) + ka);
            uint32_t bh1 = *(uint32_t*)(smem + SB_W1HI + e * (LDA * 2) + ka + 16);
            uint32_t bl0 = *(uint32_t*)(smem + SB_W1LO + e * (LDA * 2) + ka);
            uint32_t bl1 = *(uint32_t*)(smem + SB_W1LO + e * (LDA * 2) + ka + 16);
            mma16816(acc[nt], ah0, ah1, ah2, ah3, bh0, bh1);
            mma16816(acc[nt], ah0, ah1, ah2, ah3, bl0, bl1);
            mma16816(acc[nt], al0, al1, al2, al3, bh0, bh1);
        }
    }
    __syncthreads();   // all GEMM1 smem reads done before H overlays A-bf16/W1

    // ---- epilogue 1: bias + ELU, split hi/lo -> H tiles ----
#pragma unroll
    for (int nt = 0; nt < 16; nt++) {
        int c0 = nt * 8 + 2 * tg;
        float bb0 = b1s[c0], bb1 = b1s[c0 + 1];
        float v0 = acc[nt][0] + bb0, v1 = acc[nt][1] + bb1;
        float v2 = acc[nt][2] + bb0, v3 = acc[nt][3] + bb1;
        v0 = (v0 > 0.f) ? v0 : (__expf(v0) - 1.f);
        v1 = (v1 > 0.f) ? v1 : (__expf(v1) - 1.f);
        v2 = (v2 > 0.f) ? v2 : (__expf(v2) - 1.f);
        v3 = (v3 > 0.f) ? v3 : (__expf(v3) - 1.f);
        float h0 = __bfloat162float(__float2bfloat16(v0));
        float h1 = __bfloat162float(__float2bfloat16(v1));
        float h2 = __bfloat162float(__float2bfloat16(v2));
        float h3 = __bfloat162float(__float2bfloat16(v3));
        uint32_t o0 = (uint32_t)(row * LDH + c0) * 2;
        uint32_t o1 = (uint32_t)((row + 8) * LDH + c0) * 2;
        *(uint32_t*)(smem + SB_HHI + o0) = pack_bf(h0, h1);
        *(uint32_t*)(smem + SB_HLO + o0) = pack_bf(v0 - h0, v1 - h1);
        *(uint32_t*)(smem + SB_HHI + o1) = pack_bf(h2, h3);
        *(uint32_t*)(smem + SB_HLO + o1) = pack_bf(v2 - h2, v3 - h3);
    }
    __syncthreads();

    // ================= GEMM2: O(128x64) = split(H) @ split(W2^T) =================
    float acc2[8][4];
#pragma unroll
    for (int i = 0; i < 8; i++) { acc2[i][0] = acc2[i][1] = acc2[i][2] = acc2[i][3] = 0.f; }

#pragma unroll
    for (int kt = 0; kt < 8; kt++) {
        const uint32_t ka = (uint32_t)(kt * 16 + 2 * tg) * 2;
        uint32_t ah0 = *(uint32_t*)(smem + SB_HHI + (uint32_t)row * (LDH * 2) + ka);
        uint32_t ah1 = *(uint32_t*)(smem + SB_HHI + (uint32_t)(row + 8) * (LDH * 2) + ka);
        uint32_t ah2 = *(uint32_t*)(smem + SB_HHI + (uint32_t)row * (LDH * 2) + ka + 16);
        uint32_t ah3 = *(uint32_t*)(smem + SB_HHI + (uint32_t)(row + 8) * (LDH * 2) + ka + 16);
        uint32_t al0 = *(uint32_t*)(smem + SB_HLO + (uint32_t)row * (LDH * 2) + ka);
        uint32_t al1 = *(uint32_t*)(smem + SB_HLO + (uint32_t)(row + 8) * (LDH * 2) + ka);
        uint32_t al2 = *(uint32_t*)(smem + SB_HLO + (uint32_t)row * (LDH * 2) + ka + 16);
        uint32_t al3 = *(uint32_t*)(smem + SB_HLO + (uint32_t)(row + 8) * (LDH * 2) + ka + 16);
#pragma unroll
        for (int nt = 0; nt < 8; nt++) {
            const uint32_t o = (uint32_t)(nt * 8 + g);
            uint32_t bh0 = *(uint32_t*)(smem + SB_W2HI + o * (LDH * 2) + ka);
            uint32_t bh1 = *(uint32_t*)(smem + SB_W2HI + o * (LDH * 2) + ka + 16);
            uint32_t bl0 = *(uint32_t*)(smem + SB_W2LO + o * (LDH * 2) + ka);
            uint32_t bl1 = *(uint32_t*)(smem + SB_W2LO + o * (LDH * 2) + ka + 16);
            mma16816(acc2[nt], ah0, ah1, ah2, ah3, bh0, bh1);
            mma16816(acc2[nt], ah0, ah1, ah2, ah3, bl0, bl1);
            mma16816(acc2[nt], al0, al1, al2, al3, bh0, bh1);
        }
    }

    // ---- epilogue 2: + b2 + residual (in As), then coalesced store ----
#pragma unroll
    for (int nt = 0; nt < 8; nt++) {
        int c0 = nt * 8 + 2 * tg;
        float bb0 = b2s[c0], bb1 = b2s[c0 + 1];
        As[row * 68 + c0]           += acc2[nt][0] + bb0;
        As[row * 68 + c0 + 1]       += acc2[nt][1] + bb1;
        As[(row + 8) * 68 + c0]     += acc2[nt][2] + bb0;
        As[(row + 8) * 68 + c0 + 1] += acc2[nt][3] + bb1;
    }
    __syncthreads();
    {
        float* dst = act_out + row0 * DIM + (size_t)n * BLK;
        for (int idx = tid; idx < 2048; idx += 256) {
            int rr = idx >> 4, c4 = idx & 15;
            *reinterpret_cast<float4*>(dst + (size_t)rr * DIM + c4 * 4) =
                *reinterpret_cast<const float4*>(As + rr * 68 + c4 * 4);
        }
    }
}

// ============== per-row 64x64 transpose (involution) ==============
__global__ __launch_bounds__(256)
void transpose64_kernel(const float* __restrict__ in, float* __restrict__ out)
{
    __shared__ float s[64 * 65];
    const size_t base = (size_t)blockIdx.x * DIM;
    for (int idx = threadIdx.x; idx < DIM; idx += 256) {
        int a = idx >> 6, b = idx & 63;
        s[a * 65 + b] = in[base + idx];
    }
    __syncthreads();
    for (int idx = threadIdx.x; idx < DIM; idx += 256) {
        int b = idx >> 6, a = idx & 63;
        out[base + idx] = s[a * 65 + b];
    }
}

static float* symbol_addr(const void* sym)
{
    void* p = nullptr;
    cudaGetSymbolAddress(&p, sym);
    return (float*)p;
}

extern "C" void kernel_launch(void* const* d_in, const int* in_sizes, int n_in,
                              void* d_out, int out_size)
{
    (void)in_sizes; (void)n_in; (void)out_size;
    const float* x  = (const float*)d_in[0];
    const float* w1 = (const float*)d_in[1];
    const float* b1 = (const float*)d_in[2];
    const float* w2 = (const float*)d_in[3];
    const float* b2 = (const float*)d_in[4];
    float* out = (float*)d_out;

    float* bufA = symbol_addr(g_bufA);
    float* bufB = symbol_addr(g_bufB);

    cudaFuncSetAttribute((const void*)mlp_tc_kernel,
                         cudaFuncAttributeMaxDynamicSharedMemorySize, SMEM_TOTAL);

    prep_weights<<<4096, 512>>>(w1, w2);

    const dim3 grid(BS / 128, NB);
    const size_t ob1 = (size_t)NB * HID, ob2 = (size_t)NB * BLK;

    // layer 0 (gap=1 shuffle = identity)
    mlp_tc_kernel<<<grid, 256, SMEM_TOTAL>>>(x, bufA, 0, b1, b2);
    // gap=64 shuffle: per-row 64x64 transpose
    transpose64_kernel<<<BS, 256>>>(bufA, bufB);
    // layer 1
    mlp_tc_kernel<<<grid, 256, SMEM_TOTAL>>>(bufB, bufA, 1, b1 + ob1, b2 + ob2);
    // inverse shuffle
    transpose64_kernel<<<BS, 256>>>(bufA, out);
}

// round 8
// speedup vs baseline: 1.4353x; 1.3905x over previous
#include <cuda_runtime.h>
#include <cuda_bf16.h>
#include <cstdint>

#define BS   8192
#define DIM  4096
#define BLK  64
#define NB   64
#define HID  128

// ================= device scratch (no allocs allowed) =================
__device__ float g_bufA[(size_t)BS * DIM];
__device__ float g_bufB[(size_t)BS * DIM];
// prepped bf16 hi/lo weights, dense k-contiguous:
//   W1^T: [t][e=128][d=64]   W2^T: [t][o=64][e=128]     (t = layer*64 + n)
__device__ __nv_bfloat16 g_w1t_hi[2 * 64 * 8192];
__device__ __nv_bfloat16 g_w1t_lo[2 * 64 * 8192];
__device__ __nv_bfloat16 g_w2t_hi[2 * 64 * 8192];
__device__ __nv_bfloat16 g_w2t_lo[2 * 64 * 8192];

// ================= smem layout (bytes) =================
#define SB_ASF32  0
#define SB_AHI    34816
#define SB_ALO    53248
#define SB_W1HI   71680
#define SB_W1LO   90112
#define SB_HHI    34816          // H overlays A-bf16/W1 (dead after GEMM1)
#define SB_HLO    69632
#define SB_W2HI   108544
#define SB_W2LO   125952
#define SB_B1     143360
#define SB_B2     143872
#define SMEM_TOTAL 144128

#define LDA 72    // bf16 stride, A / W1^T tiles  (bank-conflict-free)
#define LDH 136   // bf16 stride, H / W2^T tiles

__device__ __forceinline__ uint32_t pack_bf(float a, float b) {
    uint32_t lo = (uint32_t)__bfloat16_as_ushort(__float2bfloat16(a));
    uint32_t hi = (uint32_t)__bfloat16_as_ushort(__float2bfloat16(b));
    return (hi << 16) | lo;
}

// D = A(16x16,row) * B(16x8,col) + D ; bf16 in, f32 accum
__device__ __forceinline__ void mma16816(float* c, uint32_t a0, uint32_t a1,
                                         uint32_t a2, uint32_t a3,
                                         uint32_t b0, uint32_t b1) {
    asm("mma.sync.aligned.m16n8k16.row.col.f32.bf16.bf16.f32 "
        "{%0,%1,%2,%3}, {%4,%5,%6,%7}, {%8,%9}, {%0,%1,%2,%3};"
        : "+f"(c[0]), "+f"(c[1]), "+f"(c[2]), "+f"(c[3])
        : "r"(a0), "r"(a1), "r"(a2), "r"(a3), "r"(b0), "r"(b1));
}

// ============== weight prep: fp32 -> transposed bf16 hi/lo ==============
__global__ void prep_weights(const float* __restrict__ w1, const float* __restrict__ w2)
{
    size_t idx = (size_t)blockIdx.x * blockDim.x + threadIdx.x;
    const size_t HALF = (size_t)2 * 64 * 64 * 128;   // 1,048,576
    if (idx < HALF) {
        int e = idx & 127, d = (idx >> 7) & 63;
        size_t t = idx >> 13;
        float v = w1[idx];
        __nv_bfloat16 h = __float2bfloat16(v);
        g_w1t_hi[t * 8192 + e * 64 + d] = h;
        g_w1t_lo[t * 8192 + e * 64 + d] = __float2bfloat16(v - __bfloat162float(h));
    } else if (idx < 2 * HALF) {
        size_t i2 = idx - HALF;
        int o = i2 & 63, e = (i2 >> 6) & 127;
        size_t t = i2 >> 13;
        float v = w2[i2];
        __nv_bfloat16 h = __float2bfloat16(v);
        g_w2t_hi[t * 8192 + o * 128 + e] = h;
        g_w2t_lo[t * 8192 + o * 128 + e] = __float2bfloat16(v - __bfloat162float(h));
    }
}

// ============== fused block MLP on HMMA, 512 threads, N-split warps ==============
__global__ __launch_bounds__(512, 1)
void mlp_tc_kernel(const float* __restrict__ act_in, float* __restrict__ act_out,
                   int layer, const float* __restrict__ b1g, const float* __restrict__ b2g)
{
    extern __shared__ unsigned char smem[];
    float* As  = (float*)(smem + SB_ASF32);
    float* b1s = (float*)(smem + SB_B1);
    float* b2s = (float*)(smem + SB_B2);

    const int tid = threadIdx.x;
    const int m = blockIdx.x, n = blockIdx.y;
    const size_t t = (size_t)layer * 64 + n;
    const size_t row0 = (size_t)m * 128;

    // ---- load A tile (128x64 fp32, coalesced) ----
    {
        const float* src = act_in + row0 * DIM + (size_t)n * BLK;
        for (int idx = tid; idx < 2048; idx += 512) {
            int rr = idx >> 4, c4 = idx & 15;
            float4 v = *reinterpret_cast<const float4*>(src + (size_t)rr * DIM + c4 * 4);
            *reinterpret_cast<float4*>(As + rr * 68 + c4 * 4) = v;
        }
    }
    // ---- copy weights into padded smem tiles ----
    {
        const uint32_t* s1h = (const uint32_t*)(g_w1t_hi + t * 8192);
        const uint32_t* s1l = (const uint32_t*)(g_w1t_lo + t * 8192);
        const uint32_t* s2h = (const uint32_t*)(g_w2t_hi + t * 8192);
        const uint32_t* s2l = (const uint32_t*)(g_w2t_lo + t * 8192);
        for (int i = tid; i < 4096; i += 512) {
            int e = i >> 5, p = i & 31;
            uint32_t doff = (uint32_t)(e * LDA + p * 2) * 2;
            *(uint32_t*)(smem + SB_W1HI + doff) = s1h[i];
            *(uint32_t*)(smem + SB_W1LO + doff) = s1l[i];
            int o = i >> 6, q = i & 63;
            uint32_t doff2 = (uint32_t)(o * LDH + q * 2) * 2;
            *(uint32_t*)(smem + SB_W2HI + doff2) = s2h[i];
            *(uint32_t*)(smem + SB_W2LO + doff2) = s2l[i];
        }
        if (tid < 128)      b1s[tid] = b1g[(size_t)n * HID + tid];
        else if (tid < 192) b2s[tid - 128] = b2g[(size_t)n * BLK + (tid - 128)];
    }
    __syncthreads();

    // ---- convert A -> bf16 hi/lo tiles (each thread: 16 cols of one row) ----
    {
        const int rr = tid & 127, hf = tid >> 7;      // hf in 0..3
#pragma unroll
        for (int j = 0; j < 8; j++) {
            int c = hf * 16 + 2 * j;
            float v0 = As[rr * 68 + c], v1 = As[rr * 68 + c + 1];
            float h0 = __bfloat162float(__float2bfloat16(v0));
            float h1 = __bfloat162float(__float2bfloat16(v1));
            uint32_t off = (uint32_t)(rr * LDA + c) * 2;
            *(uint32_t*)(smem + SB_AHI + off) = pack_bf(h0, h1);
            *(uint32_t*)(smem + SB_ALO + off) = pack_bf(v0 - h0, v1 - h1);
        }
    }
    __syncthreads();

    const int w = tid >> 5, lane = tid & 31;
    const int stripe = w >> 1, nh = w & 1;           // 8 row-stripes x 2 N-halves
    const int g = lane >> 2, tg = lane & 3;
    const int row = stripe * 16 + g;                 // fragment rows: row, row+8

    // ================= GEMM1: H(128x128) = split(A) @ split(W1^T) =================
    float acc[8][4];
#pragma unroll
    for (int i = 0; i < 8; i++) { acc[i][0] = acc[i][1] = acc[i][2] = acc[i][3] = 0.f; }

#pragma unroll
    for (int kt = 0; kt < 4; kt++) {
        const uint32_t ka = (uint32_t)(kt * 16 + 2 * tg) * 2;
        uint32_t ah0 = *(uint32_t*)(smem + SB_AHI + (uint32_t)row * (LDA * 2) + ka);
        uint32_t ah1 = *(uint32_t*)(smem + SB_AHI + (uint32_t)(row + 8) * (LDA * 2) + ka);
        uint32_t ah2 = *(uint32_t*)(smem + SB_AHI + (uint32_t)row * (LDA * 2) + ka + 16);
        uint32_t ah3 = *(uint32_t*)(smem + SB_AHI + (uint32_t)(row + 8) * (LDA * 2) + ka + 16);
        uint32_t al0 = *(uint32_t*)(smem + SB_ALO + (uint32_t)row * (LDA * 2) + ka);
        uint32_t al1 = *(uint32_t*)(smem + SB_ALO + (uint32_t)(row + 8) * (LDA * 2) + ka);
        uint32_t al2 = *(uint32_t*)(smem + SB_ALO + (uint32_t)row * (LDA * 2) + ka + 16);
        uint32_t al3 = *(uint32_t*)(smem + SB_ALO + (uint32_t)(row + 8) * (LDA * 2) + ka + 16);
#pragma unroll
        for (int nt = 0; nt < 8; nt++) {
            const uint32_t e = (uint32_t)(nh * 64 + nt * 8 + g);
            uint32_t bh0 = *(uint32_t*)(smem + SB_W1HI + e * (LDA * 2) + ka);
            uint32_t bh1 = *(uint32_t*)(smem + SB_W1HI + e * (LDA * 2) + ka + 16);
            uint32_t bl0 = *(uint32_t*)(smem + SB_W1LO + e * (LDA * 2) + ka);
            uint32_t bl1 = *(uint32_t*)(smem + SB_W1LO + e * (LDA * 2) + ka + 16);
            mma16816(acc[nt], ah0, ah1, ah2, ah3, bh0, bh1);
            mma16816(acc[nt], ah0, ah1, ah2, ah3, bl0, bl1);
            mma16816(acc[nt], al0, al1, al2, al3, bh0, bh1);
        }
    }
    __syncthreads();   // GEMM1 smem reads done before H overlays A-bf16/W1

    // ---- epilogue 1: bias + ELU, split hi/lo -> H tiles ----
#pragma unroll
    for (int nt = 0; nt < 8; nt++) {
        int c0 = nh * 64 + nt * 8 + 2 * tg;
        float bb0 = b1s[c0], bb1 = b1s[c0 + 1];
        float v0 = acc[nt][0] + bb0, v1 = acc[nt][1] + bb1;
        float v2 = acc[nt][2] + bb0, v3 = acc[nt][3] + bb1;
        v0 = (v0 > 0.f) ? v0 : (__expf(v0) - 1.f);
        v1 = (v1 > 0.f) ? v1 : (__expf(v1) - 1.f);
        v2 = (v2 > 0.f) ? v2 : (__expf(v2) - 1.f);
        v3 = (v3 > 0.f) ? v3 : (__expf(v3) - 1.f);
        float h0 = __bfloat162float(__float2bfloat16(v0));
        float h1 = __bfloat162float(__float2bfloat16(v1));
        float h2 = __bfloat162float(__float2bfloat16(v2));
        float h3 = __bfloat162float(__float2bfloat16(v3));
        uint32_t o0 = (uint32_t)(row * LDH + c0) * 2;
        uint32_t o1 = (uint32_t)((row + 8) * LDH + c0) * 2;
        *(uint32_t*)(smem + SB_HHI + o0) = pack_bf(h0, h1);
        *(uint32_t*)(smem + SB_HLO + o0) = pack_bf(v0 - h0, v1 - h1);
        *(uint32_t*)(smem + SB_HHI + o1) = pack_bf(h2, h3);
        *(uint32_t*)(smem + SB_HLO + o1) = pack_bf(v2 - h2, v3 - h3);
    }
    __syncthreads();

    // ================= GEMM2: O(128x64) = split(H) @ split(W2^T) =================
    float acc2[4][4];
#pragma unroll
    for (int i = 0; i < 4; i++) { acc2[i][0] = acc2[i][1] = acc2[i][2] = acc2[i][3] = 0.f; }

#pragma unroll
    for (int kt = 0; kt < 8; kt++) {
        const uint32_t ka = (uint32_t)(kt * 16 + 2 * tg) * 2;
        uint32_t ah0 = *(uint32_t*)(smem + SB_HHI + (uint32_t)row * (LDH * 2) + ka);
        uint32_t ah1 = *(uint32_t*)(smem + SB_HHI + (uint32_t)(row + 8) * (LDH * 2) + ka);
        uint32_t ah2 = *(uint32_t*)(smem + SB_HHI + (uint32_t)row * (LDH * 2) + ka + 16);
        uint32_t ah3 = *(uint32_t*)(smem + SB_HHI + (uint32_t)(row + 8) * (LDH * 2) + ka + 16);
        uint32_t al0 = *(uint32_t*)(smem + SB_HLO + (uint32_t)row * (LDH * 2) + ka);
        uint32_t al1 = *(uint32_t*)(smem + SB_HLO + (uint32_t)(row + 8) * (LDH * 2) + ka);
        uint32_t al2 = *(uint32_t*)(smem + SB_HLO + (uint32_t)row * (LDH * 2) + ka + 16);
        uint32_t al3 = *(uint32_t*)(smem + SB_HLO + (uint32_t)(row + 8) * (LDH * 2) + ka + 16);
#pragma unroll
        for (int nt = 0; nt < 4; nt++) {
            const uint32_t o = (uint32_t)(nh * 32 + nt * 8 + g);
            uint32_t bh0 = *(uint32_t*)(smem + SB_W2HI + o * (LDH * 2) + ka);
            uint32_t bh1 = *(uint32_t*)(smem + SB_W2HI + o * (LDH * 2) + ka + 16);
            uint32_t bl0 = *(uint32_t*)(smem + SB_W2LO + o * (LDH * 2) + ka);
            uint32_t bl1 = *(uint32_t*)(smem + SB_W2LO + o * (LDH * 2) + ka + 16);
            mma16816(acc2[nt], ah0, ah1, ah2, ah3, bh0, bh1);
            mma16816(acc2[nt], ah0, ah1, ah2, ah3, bl0, bl1);
            mma16816(acc2[nt], al0, al1, al2, al3, bh0, bh1);
        }
    }

    // ---- epilogue 2: + b2 + residual (in As), then coalesced store ----
#pragma unroll
    for (int nt = 0; nt < 4; nt++) {
        int c0 = nh * 32 + nt * 8 + 2 * tg;
        float bb0 = b2s[c0], bb1 = b2s[c0 + 1];
        As[row * 68 + c0]           += acc2[nt][0] + bb0;
        As[row * 68 + c0 + 1]       += acc2[nt][1] + bb1;
        As[(row + 8) * 68 + c0]     += acc2[nt][2] + bb0;
        As[(row + 8) * 68 + c0 + 1] += acc2[nt][3] + bb1;
    }
    __syncthreads();
    {
        float* dst = act_out + row0 * DIM + (size_t)n * BLK;
        for (int idx = tid; idx < 2048; idx += 512) {
            int rr = idx >> 4, c4 = idx & 15;
            *reinterpret_cast<float4*>(dst + (size_t)rr * DIM + c4 * 4) =
                *reinterpret_cast<const float4*>(As + rr * 68 + c4 * 4);
        }
    }
}

// ============== per-row 64x64 transpose, 2 rows/CTA, float4 both sides ==============
__global__ __launch_bounds__(256)
void transpose64_kernel(const float* __restrict__ in, float* __restrict__ out)
{
    __shared__ float s[2][64 * 65];
    const size_t base = (size_t)blockIdx.x * 2 * DIM;
    const int tid = threadIdx.x;
    // load: s[r][a*65 + b] = in[row r][a*64 + b], vectorized gmem reads
    for (int i = tid; i < 2048; i += 256) {
        int r = i >> 10, j = i & 1023;
        int a = j >> 4, q = j & 15;
        float4 v = *reinterpret_cast<const float4*>(in + base + (size_t)r * DIM + a * 64 + q * 4);
        float* sp = &s[r][a * 65 + q * 4];
        sp[0] = v.x; sp[1] = v.y; sp[2] = v.z; sp[3] = v.w;
    }
    __syncthreads();
    // store: out[row r][b*64 + a] = s[r][a*65 + b], vectorized gmem writes
    for (int i = tid; i < 2048; i += 256) {
        int r = i >> 10, j = i & 1023;
        int b = j >> 4, q = j & 15;
        float4 v;
        v.x = s[r][(q * 4 + 0) * 65 + b];
        v.y = s[r][(q * 4 + 1) * 65 + b];
        v.z = s[r][(q * 4 + 2) * 65 + b];
        v.w = s[r][(q * 4 + 3) * 65 + b];
        *reinterpret_cast<float4*>(out + base + (size_t)r * DIM + b * 64 + q * 4) = v;
    }
}

static float* symbol_addr(const void* sym)
{
    void* p = nullptr;
    cudaGetSymbolAddress(&p, sym);
    return (float*)p;
}

extern "C" void kernel_launch(void* const* d_in, const int* in_sizes, int n_in,
                              void* d_out, int out_size)
{
    (void)in_sizes; (void)n_in; (void)out_size;
    const float* x  = (const float*)d_in[0];
    const float* w1 = (const float*)d_in[1];
    const float* b1 = (const float*)d_in[2];
    const float* w2 = (const float*)d_in[3];
    const float* b2 = (const float*)d_in[4];
    float* out = (float*)d_out;

    float* bufA = symbol_addr(g_bufA);
    float* bufB = symbol_addr(g_bufB);

    cudaFuncSetAttribute((const void*)mlp_tc_kernel,
                         cudaFuncAttributeMaxDynamicSharedMemorySize, SMEM_TOTAL);

    prep_weights<<<4096, 512>>>(w1, w2);

    const dim3 grid(BS / 128, NB);
    const size_t ob1 = (size_t)NB * HID, ob2 = (size_t)NB * BLK;

    // layer 0 (gap=1 shuffle = identity)
    mlp_tc_kernel<<<grid, 512, SMEM_TOTAL>>>(x, bufA, 0, b1, b2);
    // gap=64 shuffle: per-row 64x64 transpose
    transpose64_kernel<<<BS / 2, 256>>>(bufA, bufB);
    // layer 1
    mlp_tc_kernel<<<grid, 512, SMEM_TOTAL>>>(bufB, bufA, 1, b1 + ob1, b2 + ob2);
    // inverse shuffle
    transpose64_kernel<<<BS / 2, 256>>>(bufA, out);
}

// round 10
// speedup vs baseline: 2.0339x; 1.4171x over previous
#include <cuda_runtime.h>
#include <cuda_bf16.h>
#include <cstdint>

#define BS   8192
#define DIM  4096
#define BLK  64
#define NB   64
#define HID  128

// ================= device scratch (no allocs allowed) =================
__device__ float g_bufA[(size_t)BS * DIM];
__device__ float g_bufB[(size_t)BS * DIM];
// prepped bf16 hi/lo weights, dense k-contiguous:
//   W1^T: [t][e=128][d=64]   W2^T: [t][o=64][e=128]     (t = layer*64 + n)
__device__ __nv_bfloat16 g_w1t_hi[2 * 64 * 8192];
__device__ __nv_bfloat16 g_w1t_lo[2 * 64 * 8192];
__device__ __nv_bfloat16 g_w2t_hi[2 * 64 * 8192];
__device__ __nv_bfloat16 g_w2t_lo[2 * 64 * 8192];

// ================= smem layout (bytes) =================
// Phase 1 (until GEMM1 done):  A hi/lo [0,36864)  W1 hi/lo [36864,73728)
// Phase 2 (GEMM2):             H hi/lo [0,69632)   (overlays A+W1)
// Phase 3 (store):             OUT fp32 [0,34816)  (overlays H-hi)
// Always:                      W2 hi/lo [73728,108544)  b1/b2 [108544,109312)
#define SB_AHI    0
#define SB_ALO    18432
#define SB_W1HI   36864
#define SB_W1LO   55296
#define SB_HHI    0
#define SB_HLO    34816
#define SB_OUT    0
#define SB_W2HI   73728
#define SB_W2LO   91136
#define SB_B1     108544
#define SB_B2     109056
#define SMEM_TOTAL 109312

#define LDA 72    // bf16 stride, A / W1^T tiles  (bank-conflict-free)
#define LDH 136   // bf16 stride, H / W2^T tiles

__device__ __forceinline__ uint32_t pack_bf(float a, float b) {
    uint32_t lo = (uint32_t)__bfloat16_as_ushort(__float2bfloat16(a));
    uint32_t hi = (uint32_t)__bfloat16_as_ushort(__float2bfloat16(b));
    return (hi << 16) | lo;
}

// D = A(16x16,row) * B(16x8,col) + D ; bf16 in, f32 accum
__device__ __forceinline__ void mma16816(float* c, uint32_t a0, uint32_t a1,
                                         uint32_t a2, uint32_t a3,
                                         uint32_t b0, uint32_t b1) {
    asm("mma.sync.aligned.m16n8k16.row.col.f32.bf16.bf16.f32 "
        "{%0,%1,%2,%3}, {%4,%5,%6,%7}, {%8,%9}, {%0,%1,%2,%3};"
        : "+f"(c[0]), "+f"(c[1]), "+f"(c[2]), "+f"(c[3])
        : "r"(a0), "r"(a1), "r"(a2), "r"(a3), "r"(b0), "r"(b1));
}

// ============== weight prep: fp32 -> transposed bf16 hi/lo ==============
__global__ void prep_weights(const float* __restrict__ w1, const float* __restrict__ w2)
{
    size_t idx = (size_t)blockIdx.x * blockDim.x + threadIdx.x;
    const size_t HALF = (size_t)2 * 64 * 64 * 128;   // 1,048,576
    if (idx < HALF) {
        int e = idx & 127, d = (idx >> 7) & 63;
        size_t t = idx >> 13;
        float v = w1[idx];
        __nv_bfloat16 h = __float2bfloat16(v);
        g_w1t_hi[t * 8192 + e * 64 + d] = h;
        g_w1t_lo[t * 8192 + e * 64 + d] = __float2bfloat16(v - __bfloat162float(h));
    } else if (idx < 2 * HALF) {
        size_t i2 = idx - HALF;
        int o = i2 & 63, e = (i2 >> 6) & 127;
        size_t t = i2 >> 13;
        float v = w2[i2];
        __nv_bfloat16 h = __float2bfloat16(v);
        g_w2t_hi[t * 8192 + o * 128 + e] = h;
        g_w2t_lo[t * 8192 + o * 128 + e] = __float2bfloat16(v - __bfloat162float(h));
    }
}

// ============== fused block MLP on HMMA, 512 thr, 2 CTAs/SM ==============
__global__ __launch_bounds__(512, 2)
void mlp_tc_kernel(const float* __restrict__ act_in, float* __restrict__ act_out,
                   int layer, const float* __restrict__ b1g, const float* __restrict__ b2g)
{
    extern __shared__ unsigned char smem[];
    float* b1s = (float*)(smem + SB_B1);
    float* b2s = (float*)(smem + SB_B2);
    float* Os  = (float*)(smem + SB_OUT);

    const int tid = threadIdx.x;
    const int m = blockIdx.x, n = blockIdx.y;
    const size_t t = (size_t)layer * 64 + n;
    const size_t row0 = (size_t)m * 128;

    // ---- load A tile + convert to bf16 hi/lo inline (no fp32 staging) ----
    {
        const float* src = act_in + row0 * DIM + (size_t)n * BLK;
        for (int idx = tid; idx < 2048; idx += 512) {
            int rr = idx >> 4, c4 = idx & 15;
            float4 v = *reinterpret_cast<const float4*>(src + (size_t)rr * DIM + c4 * 4);
            float h0 = __bfloat162float(__float2bfloat16(v.x));
            float h1 = __bfloat162float(__float2bfloat16(v.y));
            float h2 = __bfloat162float(__float2bfloat16(v.z));
            float h3 = __bfloat162float(__float2bfloat16(v.w));
            uint2 hi, lo;
            hi.x = pack_bf(h0, h1);       hi.y = pack_bf(h2, h3);
            lo.x = pack_bf(v.x - h0, v.y - h1);
            lo.y = pack_bf(v.z - h2, v.w - h3);
            uint32_t off = (uint32_t)(rr * LDA + c4 * 4) * 2;
            *(uint2*)(smem + SB_AHI + off) = hi;
            *(uint2*)(smem + SB_ALO + off) = lo;
        }
    }
    // ---- copy weights into padded smem tiles ----
    {
        const uint32_t* s1h = (const uint32_t*)(g_w1t_hi + t * 8192);
        const uint32_t* s1l = (const uint32_t*)(g_w1t_lo + t * 8192);
        const uint32_t* s2h = (const uint32_t*)(g_w2t_hi + t * 8192);
        const uint32_t* s2l = (const uint32_t*)(g_w2t_lo + t * 8192);
        for (int i = tid; i < 4096; i += 512) {
            int e = i >> 5, p = i & 31;
            uint32_t doff = (uint32_t)(e * LDA + p * 2) * 2;
            *(uint32_t*)(smem + SB_W1HI + doff) = s1h[i];
            *(uint32_t*)(smem + SB_W1LO + doff) = s1l[i];
            int o = i >> 6, q = i & 63;
            uint32_t doff2 = (uint32_t)(o * LDH + q * 2) * 2;
            *(uint32_t*)(smem + SB_W2HI + doff2) = s2h[i];
            *(uint32_t*)(smem + SB_W2LO + doff2) = s2l[i];
        }
        if (tid < 128)      b1s[tid] = b1g[(size_t)n * HID + tid];
        else if (tid < 192) b2s[tid - 128] = b2g[(size_t)n * BLK + (tid - 128)];
    }
    __syncthreads();

    const int w = tid >> 5, lane = tid & 31;
    const int stripe = w >> 1, nh = w & 1;           // 8 row-stripes x 2 N-halves
    const int g = lane >> 2, tg = lane & 3;
    const int row = stripe * 16 + g;                 // fragment rows: row, row+8

    // ================= GEMM1: H(128x128) = split(A) @ split(W1^T) =================
    float acc[8][4];
#pragma unroll
    for (int i = 0; i < 8; i++) { acc[i][0] = acc[i][1] = acc[i][2] = acc[i][3] = 0.f; }

#pragma unroll
    for (int kt = 0; kt < 4; kt++) {
        const uint32_t ka = (uint32_t)(kt * 16 + 2 * tg) * 2;
        uint32_t ah0 = *(uint32_t*)(smem + SB_AHI + (uint32_t)row * (LDA * 2) + ka);
        uint32_t ah1 = *(uint32_t*)(smem + SB_AHI + (uint32_t)(row + 8) * (LDA * 2) + ka);
        uint32_t ah2 = *(uint32_t*)(smem + SB_AHI + (uint32_t)row * (LDA * 2) + ka + 16);
        uint32_t ah3 = *(uint32_t*)(smem + SB_AHI + (uint32_t)(row + 8) * (LDA * 2) + ka + 16);
        uint32_t al0 = *(uint32_t*)(smem + SB_ALO + (uint32_t)row * (LDA * 2) + ka);
        uint32_t al1 = *(uint32_t*)(smem + SB_ALO + (uint32_t)(row + 8) * (LDA * 2) + ka);
        uint32_t al2 = *(uint32_t*)(smem + SB_ALO + (uint32_t)row * (LDA * 2) + ka + 16);
        uint32_t al3 = *(uint32_t*)(smem + SB_ALO + (uint32_t)(row + 8) * (LDA * 2) + ka + 16);
#pragma unroll
        for (int nt = 0; nt < 8; nt++) {
            const uint32_t e = (uint32_t)(nh * 64 + nt * 8 + g);
            uint32_t bh0 = *(uint32_t*)(smem + SB_W1HI + e * (LDA * 2) + ka);
            uint32_t bh1 = *(uint32_t*)(smem + SB_W1HI + e * (LDA * 2) + ka + 16);
            uint32_t bl0 = *(uint32_t*)(smem + SB_W1LO + e * (LDA * 2) + ka);
            uint32_t bl1 = *(uint32_t*)(smem + SB_W1LO + e * (LDA * 2) + ka + 16);
            mma16816(acc[nt], ah0, ah1, ah2, ah3, bh0, bh1);
            mma16816(acc[nt], ah0, ah1, ah2, ah3, bl0, bl1);
            mma16816(acc[nt], al0, al1, al2, al3, bh0, bh1);
        }
    }
    __syncthreads();   // GEMM1 smem reads done before H overlays A/W1

    // ---- epilogue 1: bias + ELU, split hi/lo -> H tiles ----
#pragma unroll
    for (int nt = 0; nt < 8; nt++) {
        int c0 = nh * 64 + nt * 8 + 2 * tg;
        float bb0 = b1s[c0], bb1 = b1s[c0 + 1];
        float v0 = acc[nt][0] + bb0, v1 = acc[nt][1] + bb1;
        float v2 = acc[nt][2] + bb0, v3 = acc[nt][3] + bb1;
        v0 = (v0 > 0.f) ? v0 : (__expf(v0) - 1.f);
        v1 = (v1 > 0.f) ? v1 : (__expf(v1) - 1.f);
        v2 = (v2 > 0.f) ? v2 : (__expf(v2) - 1.f);
        v3 = (v3 > 0.f) ? v3 : (__expf(v3) - 1.f);
        float h0 = __bfloat162float(__float2bfloat16(v0));
        float h1 = __bfloat162float(__float2bfloat16(v1));
        float h2 = __bfloat162float(__float2bfloat16(v2));
        float h3 = __bfloat162float(__float2bfloat16(v3));
        uint32_t o0 = (uint32_t)(row * LDH + c0) * 2;
        uint32_t o1 = (uint32_t)((row + 8) * LDH + c0) * 2;
        *(uint32_t*)(smem + SB_HHI + o0) = pack_bf(h0, h1);
        *(uint32_t*)(smem + SB_HLO + o0) = pack_bf(v0 - h0, v1 - h1);
        *(uint32_t*)(smem + SB_HHI + o1) = pack_bf(h2, h3);
        *(uint32_t*)(smem + SB_HLO + o1) = pack_bf(v2 - h2, v3 - h3);
    }
    __syncthreads();

    // ================= GEMM2: O(128x64) = split(H) @ split(W2^T) =================
    float acc2[4][4];
#pragma unroll
    for (int i = 0; i < 4; i++) { acc2[i][0] = acc2[i][1] = acc2[i][2] = acc2[i][3] = 0.f; }

#pragma unroll
    for (int kt = 0; kt < 8; kt++) {
        const uint32_t ka = (uint32_t)(kt * 16 + 2 * tg) * 2;
        uint32_t ah0 = *(uint32_t*)(smem + SB_HHI + (uint32_t)row * (LDH * 2) + ka);
        uint32_t ah1 = *(uint32_t*)(smem + SB_HHI + (uint32_t)(row + 8) * (LDH * 2) + ka);
        uint32_t ah2 = *(uint32_t*)(smem + SB_HHI + (uint32_t)row * (LDH * 2) + ka + 16);
        uint32_t ah3 = *(uint32_t*)(smem + SB_HHI + (uint32_t)(row + 8) * (LDH * 2) + ka + 16);
        uint32_t al0 = *(uint32_t*)(smem + SB_HLO + (uint32_t)row * (LDH * 2) + ka);
        uint32_t al1 = *(uint32_t*)(smem + SB_HLO + (uint32_t)(row + 8) * (LDH * 2) + ka);
        uint32_t al2 = *(uint32_t*)(smem + SB_HLO + (uint32_t)row * (LDH * 2) + ka + 16);
        uint32_t al3 = *(uint32_t*)(smem + SB_HLO + (uint32_t)(row + 8) * (LDH * 2) + ka + 16);
#pragma unroll
        for (int nt = 0; nt < 4; nt++) {
            const uint32_t o = (uint32_t)(nh * 32 + nt * 8 + g);
            uint32_t bh0 = *(uint32_t*)(smem + SB_W2HI + o * (LDH * 2) + ka);
            uint32_t bh1 = *(uint32_t*)(smem + SB_W2HI + o * (LDH * 2) + ka + 16);
            uint32_t bl0 = *(uint32_t*)(smem + SB_W2LO + o * (LDH * 2) + ka);
            uint32_t bl1 = *(uint32_t*)(smem + SB_W2LO + o * (LDH * 2) + ka + 16);
            mma16816(acc2[nt], ah0, ah1, ah2, ah3, bh0, bh1);
            mma16816(acc2[nt], ah0, ah1, ah2, ah3, bl0, bl1);
            mma16816(acc2[nt], al0, al1, al2, al3, bh0, bh1);
        }
    }
    __syncthreads();   // all GEMM2 H reads done before OUT overlays H

    // ---- epilogue 2: acc2 + b2 -> OUT smem (residual added in store pass) ----
#pragma unroll
    for (int nt = 0; nt < 4; nt++) {
        int c0 = nh * 32 + nt * 8 + 2 * tg;
        float bb0 = b2s[c0], bb1 = b2s[c0 + 1];
        Os[row * 68 + c0]           = acc2[nt][0] + bb0;
        Os[row * 68 + c0 + 1]       = acc2[nt][1] + bb1;
        Os[(row + 8) * 68 + c0]     = acc2[nt][2] + bb0;
        Os[(row + 8) * 68 + c0 + 1] = acc2[nt][3] + bb1;
    }
    __syncthreads();

    // ---- store: OUT + residual (re-read from gmem, coalesced) ----
    {
        const float* rsrc = act_in + row0 * DIM + (size_t)n * BLK;
        float* dst = act_out + row0 * DIM + (size_t)n * BLK;
        for (int idx = tid; idx < 2048; idx += 512) {
            int rr = idx >> 4, c4 = idx & 15;
            float4 o = *reinterpret_cast<const float4*>(Os + rr * 68 + c4 * 4);
            float4 a = *reinterpret_cast<const float4*>(rsrc + (size_t)rr * DIM + c4 * 4);
            o.x += a.x; o.y += a.y; o.z += a.z; o.w += a.w;
            *reinterpret_cast<float4*>(dst + (size_t)rr * DIM + c4 * 4) = o;
        }
    }
}

// ============== per-row 64x64 transpose, 2 rows/CTA, float4 both sides ==============
__global__ __launch_bounds__(256)
void transpose64_kernel(const float* __restrict__ in, float* __restrict__ out)
{
    __shared__ float s[2][64 * 65];
    const size_t base = (size_t)blockIdx.x * 2 * DIM;
    const int tid = threadIdx.x;
    for (int i = tid; i < 2048; i += 256) {
        int r = i >> 10, j = i & 1023;
        int a = j >> 4, q = j & 15;
        float4 v = *reinterpret_cast<const float4*>(in + base + (size_t)r * DIM + a * 64 + q * 4);
        float* sp = &s[r][a * 65 + q * 4];
        sp[0] = v.x; sp[1] = v.y; sp[2] = v.z; sp[3] = v.w;
    }
    __syncthreads();
    for (int i = tid; i < 2048; i += 256) {
        int r = i >> 10, j = i & 1023;
        int b = j >> 4, q = j & 15;
        float4 v;
        v.x = s[r][(q * 4 + 0) * 65 + b];
        v.y = s[r][(q * 4 + 1) * 65 + b];
        v.z = s[r][(q * 4 + 2) * 65 + b];
        v.w = s[r][(q * 4 + 3) * 65 + b];
        *reinterpret_cast<float4*>(out + base + (size_t)r * DIM + b * 64 + q * 4) = v;
    }
}

static float* symbol_addr(const void* sym)
{
    void* p = nullptr;
    cudaGetSymbolAddress(&p, sym);
    return (float*)p;
}

extern "C" void kernel_launch(void* const* d_in, const int* in_sizes, int n_in,
                              void* d_out, int out_size)
{
    (void)in_sizes; (void)n_in; (void)out_size;
    const float* x  = (const float*)d_in[0];
    const float* w1 = (const float*)d_in[1];
    const float* b1 = (const float*)d_in[2];
    const float* w2 = (const float*)d_in[3];
    const float* b2 = (const float*)d_in[4];
    float* out = (float*)d_out;

    float* bufA = symbol_addr(g_bufA);
    float* bufB = symbol_addr(g_bufB);

    cudaFuncSetAttribute((const void*)mlp_tc_kernel,
                         cudaFuncAttributeMaxDynamicSharedMemorySize, SMEM_TOTAL);

    prep_weights<<<4096, 512>>>(w1, w2);

    const dim3 grid(BS / 128, NB);
    const size_t ob1 = (size_t)NB * HID, ob2 = (size_t)NB * BLK;

    // layer 0 (gap=1 shuffle = identity)
    mlp_tc_kernel<<<grid, 512, SMEM_TOTAL>>>(x, bufA, 0, b1, b2);
    // gap=64 shuffle: per-row 64x64 transpose
    transpose64_kernel<<<BS / 2, 256>>>(bufA, bufB);
    // layer 1
    mlp_tc_kernel<<<grid, 512, SMEM_TOTAL>>>(bufB, bufA, 1, b1 + ob1, b2 + ob2);
    // inverse shuffle
    transpose64_kernel<<<BS / 2, 256>>>(bufA, out);
}

// round 11
// speedup vs baseline: 2.0577x; 1.0117x over previous
#include <cuda_runtime.h>
#include <cuda_bf16.h>
#include <cstdint>

#define BS   8192
#define DIM  4096
#define BLK  64
#define NB   64
#define HID  128

// ================= device scratch (no allocs allowed) =================
__device__ float g_bufA[(size_t)BS * DIM];
__device__ float g_bufB[(size_t)BS * DIM];
// prepped bf16 hi/lo weights, dense k-contiguous:
//   W1^T: [t][e=128][d=64]   W2^T: [t][o=64][e=128]     (t = layer*64 + n)
__device__ __nv_bfloat16 g_w1t_hi[2 * 64 * 8192];
__device__ __nv_bfloat16 g_w1t_lo[2 * 64 * 8192];
__device__ __nv_bfloat16 g_w2t_hi[2 * 64 * 8192];
__device__ __nv_bfloat16 g_w2t_lo[2 * 64 * 8192];

// ================= smem layout (bytes) =================
#define SB_AHI    0
#define SB_ALO    18432
#define SB_W1HI   36864
#define SB_W1LO   55296
#define SB_HHI    0
#define SB_HLO    34816
#define SB_OUT    0
#define SB_W2HI   73728
#define SB_W2LO   91136
#define SB_B1     108544
#define SB_B2     109056
#define SMEM_TOTAL 109312

#define LDA 72    // bf16 stride, A / W1^T  (144 B: 4-bank shift/row -> LDSM conflict-free)
#define LDH 136   // bf16 stride, H / W2^T  (272 B: ditto)

__device__ __forceinline__ uint32_t smem_u32(const void* p) {
    uint32_t a;
    asm("{ .reg .u64 t; cvta.to.shared.u64 t, %1; cvt.u32.u64 %0, t; }" : "=r"(a) : "l"(p));
    return a;
}

__device__ __forceinline__ uint32_t pack_bf(float a, float b) {
    uint32_t lo = (uint32_t)__bfloat16_as_ushort(__float2bfloat16(a));
    uint32_t hi = (uint32_t)__bfloat16_as_ushort(__float2bfloat16(b));
    return (hi << 16) | lo;
}

__device__ __forceinline__ void mma16816(float* c, uint32_t a0, uint32_t a1,
                                         uint32_t a2, uint32_t a3,
                                         uint32_t b0, uint32_t b1) {
    asm("mma.sync.aligned.m16n8k16.row.col.f32.bf16.bf16.f32 "
        "{%0,%1,%2,%3}, {%4,%5,%6,%7}, {%8,%9}, {%0,%1,%2,%3};"
        : "+f"(c[0]), "+f"(c[1]), "+f"(c[2]), "+f"(c[3])
        : "r"(a0), "r"(a1), "r"(a2), "r"(a3), "r"(b0), "r"(b1));
}

__device__ __forceinline__ void ldsm4(uint32_t& r0, uint32_t& r1, uint32_t& r2,
                                      uint32_t& r3, uint32_t addr) {
    asm volatile("ldmatrix.sync.aligned.m8n8.x4.shared.b16 {%0,%1,%2,%3}, [%4];"
                 : "=r"(r0), "=r"(r1), "=r"(r2), "=r"(r3) : "r"(addr));
}

// ============== weight prep: fp32 -> transposed bf16 hi/lo ==============
__global__ void prep_weights(const float* __restrict__ w1, const float* __restrict__ w2)
{
    size_t idx = (size_t)blockIdx.x * blockDim.x + threadIdx.x;
    const size_t HALF = (size_t)2 * 64 * 64 * 128;   // 1,048,576
    if (idx < HALF) {
        int e = idx & 127, d = (idx >> 7) & 63;
        size_t t = idx >> 13;
        float v = w1[idx];
        __nv_bfloat16 h = __float2bfloat16(v);
        g_w1t_hi[t * 8192 + e * 64 + d] = h;
        g_w1t_lo[t * 8192 + e * 64 + d] = __float2bfloat16(v - __bfloat162float(h));
    } else if (idx < 2 * HALF) {
        size_t i2 = idx - HALF;
        int o = i2 & 63, e = (i2 >> 6) & 127;
        size_t t = i2 >> 13;
        float v = w2[i2];
        __nv_bfloat16 h = __float2bfloat16(v);
        g_w2t_hi[t * 8192 + o * 128 + e] = h;
        g_w2t_lo[t * 8192 + o * 128 + e] = __float2bfloat16(v - __bfloat162float(h));
    }
}

// ============== fused block MLP: HMMA + ldmatrix, 512 thr, 2 CTAs/SM ==============
__global__ __launch_bounds__(512, 2)
void mlp_tc_kernel(const float* __restrict__ act_in, float* __restrict__ act_out,
                   int layer, const float* __restrict__ b1g, const float* __restrict__ b2g)
{
    extern __shared__ unsigned char smem[];
    float* b1s = (float*)(smem + SB_B1);
    float* b2s = (float*)(smem + SB_B2);
    float* Os  = (float*)(smem + SB_OUT);
    const uint32_t sb = smem_u32(smem);

    const int tid = threadIdx.x;
    const int m = blockIdx.x, n = blockIdx.y;
    const size_t t = (size_t)layer * 64 + n;
    const size_t row0 = (size_t)m * 128;

    // ---- load A tile + convert to bf16 hi/lo inline ----
    {
        const float* src = act_in + row0 * DIM + (size_t)n * BLK;
        for (int idx = tid; idx < 2048; idx += 512) {
            int rr = idx >> 4, c4 = idx & 15;
            float4 v = *reinterpret_cast<const float4*>(src + (size_t)rr * DIM + c4 * 4);
            float h0 = __bfloat162float(__float2bfloat16(v.x));
            float h1 = __bfloat162float(__float2bfloat16(v.y));
            float h2 = __bfloat162float(__float2bfloat16(v.z));
            float h3 = __bfloat162float(__float2bfloat16(v.w));
            uint2 hi, lo;
            hi.x = pack_bf(h0, h1);       hi.y = pack_bf(h2, h3);
            lo.x = pack_bf(v.x - h0, v.y - h1);
            lo.y = pack_bf(v.z - h2, v.w - h3);
            uint32_t off = (uint32_t)(rr * LDA + c4 * 4) * 2;
            *(uint2*)(smem + SB_AHI + off) = hi;
            *(uint2*)(smem + SB_ALO + off) = lo;
        }
    }
    // ---- copy weights into padded smem tiles ----
    {
        const uint32_t* s1h = (const uint32_t*)(g_w1t_hi + t * 8192);
        const uint32_t* s1l = (const uint32_t*)(g_w1t_lo + t * 8192);
        const uint32_t* s2h = (const uint32_t*)(g_w2t_hi + t * 8192);
        const uint32_t* s2l = (const uint32_t*)(g_w2t_lo + t * 8192);
        for (int i = tid; i < 4096; i += 512) {
            int e = i >> 5, p = i & 31;
            uint32_t doff = (uint32_t)(e * LDA + p * 2) * 2;
            *(uint32_t*)(smem + SB_W1HI + doff) = s1h[i];
            *(uint32_t*)(smem + SB_W1LO + doff) = s1l[i];
            int o = i >> 6, q = i & 63;
            uint32_t doff2 = (uint32_t)(o * LDH + q * 2) * 2;
            *(uint32_t*)(smem + SB_W2HI + doff2) = s2h[i];
            *(uint32_t*)(smem + SB_W2LO + doff2) = s2l[i];
        }
        if (tid < 128)      b1s[tid] = b1g[(size_t)n * HID + tid];
        else if (tid < 192) b2s[tid - 128] = b2g[(size_t)n * BLK + (tid - 128)];
    }
    __syncthreads();

    const int w = tid >> 5, lane = tid & 31;
    const int stripe = w >> 1, nh = w & 1;           // 8 row-stripes x 2 N-halves
    const int g = lane >> 2, tg = lane & 3;
    const int row = stripe * 16 + g;

    // ldmatrix address bases
    // A/H x4: lane -> row stripe*16 + (lane&15), k-half (lane>>4)
    const uint32_t arow = (uint32_t)(stripe * 16 + (lane & 15));
    const uint32_t akh  = (uint32_t)((lane >> 4) << 4);           // 0 or 16 bytes
    const uint32_t baseAhi = sb + SB_AHI + arow * (LDA * 2) + akh;
    const uint32_t baseAlo = sb + SB_ALO + arow * (LDA * 2) + akh;
    // B x4 packs two nt tiles: lane -> m_idx = lane>>3
    const uint32_t bmi  = (uint32_t)(lane >> 3);
    const uint32_t bkh  = (bmi & 1) << 4;                         // k-half bytes
    const uint32_t brow1 = (uint32_t)(nh * 64 + ((bmi >> 1) << 3) + (lane & 7));
    const uint32_t baseW1hi = sb + SB_W1HI + brow1 * (LDA * 2) + bkh;
    const uint32_t baseW1lo = sb + SB_W1LO + brow1 * (LDA * 2) + bkh;

    // ================= GEMM1: H(128x128) = split(A) @ split(W1^T) =================
    float acc[8][4];
#pragma unroll
    for (int i = 0; i < 8; i++) { acc[i][0] = acc[i][1] = acc[i][2] = acc[i][3] = 0.f; }

#pragma unroll
    for (int kt = 0; kt < 4; kt++) {
        const uint32_t ko = (uint32_t)kt * 32;
        uint32_t ah0, ah1, ah2, ah3, al0, al1, al2, al3;
        ldsm4(ah0, ah1, ah2, ah3, baseAhi + ko);
        ldsm4(al0, al1, al2, al3, baseAlo + ko);
#pragma unroll
        for (int p = 0; p < 4; p++) {                 // nt pair (2p, 2p+1)
            uint32_t bh0a, bh1a, bh0b, bh1b, bl0a, bl1a, bl0b, bl1b;
            ldsm4(bh0a, bh1a, bh0b, bh1b, baseW1hi + (uint32_t)p * (16 * LDA * 2) + ko);
            ldsm4(bl0a, bl1a, bl0b, bl1b, baseW1lo + (uint32_t)p * (16 * LDA * 2) + ko);
            mma16816(acc[2 * p],     ah0, ah1, ah2, ah3, bh0a, bh1a);
            mma16816(acc[2 * p],     ah0, ah1, ah2, ah3, bl0a, bl1a);
            mma16816(acc[2 * p],     al0, al1, al2, al3, bh0a, bh1a);
            mma16816(acc[2 * p + 1], ah0, ah1, ah2, ah3, bh0b, bh1b);
            mma16816(acc[2 * p + 1], ah0, ah1, ah2, ah3, bl0b, bl1b);
            mma16816(acc[2 * p + 1], al0, al1, al2, al3, bh0b, bh1b);
        }
    }
    __syncthreads();   // GEMM1 smem reads done before H overlays A/W1

    // ---- epilogue 1: bias + ELU, split hi/lo -> H tiles ----
#pragma unroll
    for (int nt = 0; nt < 8; nt++) {
        int c0 = nh * 64 + nt * 8 + 2 * tg;
        float bb0 = b1s[c0], bb1 = b1s[c0 + 1];
        float v0 = acc[nt][0] + bb0, v1 = acc[nt][1] + bb1;
        float v2 = acc[nt][2] + bb0, v3 = acc[nt][3] + bb1;
        v0 = (v0 > 0.f) ? v0 : (__expf(v0) - 1.f);
        v1 = (v1 > 0.f) ? v1 : (__expf(v1) - 1.f);
        v2 = (v2 > 0.f) ? v2 : (__expf(v2) - 1.f);
        v3 = (v3 > 0.f) ? v3 : (__expf(v3) - 1.f);
        float h0 = __bfloat162float(__float2bfloat16(v0));
        float h1 = __bfloat162float(__float2bfloat16(v1));
        float h2 = __bfloat162float(__float2bfloat16(v2));
        float h3 = __bfloat162float(__float2bfloat16(v3));
        uint32_t o0 = (uint32_t)(row * LDH + c0) * 2;
        uint32_t o1 = (uint32_t)((row + 8) * LDH + c0) * 2;
        *(uint32_t*)(smem + SB_HHI + o0) = pack_bf(h0, h1);
        *(uint32_t*)(smem + SB_HLO + o0) = pack_bf(v0 - h0, v1 - h1);
        *(uint32_t*)(smem + SB_HHI + o1) = pack_bf(h2, h3);
        *(uint32_t*)(smem + SB_HLO + o1) = pack_bf(v2 - h2, v3 - h3);
    }
    __syncthreads();

    // ================= GEMM2: O(128x64) = split(H) @ split(W2^T) =================
    float acc2[4][4];
#pragma unroll
    for (int i = 0; i < 4; i++) { acc2[i][0] = acc2[i][1] = acc2[i][2] = acc2[i][3] = 0.f; }

    const uint32_t baseHhi = sb + SB_HHI + arow * (LDH * 2) + akh;
    const uint32_t baseHlo = sb + SB_HLO + arow * (LDH * 2) + akh;
    const uint32_t brow2 = (uint32_t)(nh * 32 + ((bmi >> 1) << 3) + (lane & 7));
    const uint32_t baseW2hi = sb + SB_W2HI + brow2 * (LDH * 2) + bkh;
    const uint32_t baseW2lo = sb + SB_W2LO + brow2 * (LDH * 2) + bkh;

#pragma unroll
    for (int kt = 0; kt < 8; kt++) {
        const uint32_t ko = (uint32_t)kt * 32;
        uint32_t ah0, ah1, ah2, ah3, al0, al1, al2, al3;
        ldsm4(ah0, ah1, ah2, ah3, baseHhi + ko);
        ldsm4(al0, al1, al2, al3, baseHlo + ko);
#pragma unroll
        for (int p = 0; p < 2; p++) {                 // nt pair (2p, 2p+1)
            uint32_t bh0a, bh1a, bh0b, bh1b, bl0a, bl1a, bl0b, bl1b;
            ldsm4(bh0a, bh1a, bh0b, bh1b, baseW2hi + (uint32_t)p * (16 * LDH * 2) + ko);
            ldsm4(bl0a, bl1a, bl0b, bl1b, baseW2lo + (uint32_t)p * (16 * LDH * 2) + ko);
            mma16816(acc2[2 * p],     ah0, ah1, ah2, ah3, bh0a, bh1a);
            mma16816(acc2[2 * p],     ah0, ah1, ah2, ah3, bl0a, bl1a);
            mma16816(acc2[2 * p],     al0, al1, al2, al3, bh0a, bh1a);
            mma16816(acc2[2 * p + 1], ah0, ah1, ah2, ah3, bh0b, bh1b);
            mma16816(acc2[2 * p + 1], ah0, ah1, ah2, ah3, bl0b, bl1b);
            mma16816(acc2[2 * p + 1], al0, al1, al2, al3, bh0b, bh1b);
        }
    }
    __syncthreads();   // all GEMM2 H reads done before OUT overlays H

    // ---- epilogue 2: acc2 + b2 -> OUT smem ----
#pragma unroll
    for (int nt = 0; nt < 4; nt++) {
        int c0 = nh * 32 + nt * 8 + 2 * tg;
        float bb0 = b2s[c0], bb1 = b2s[c0 + 1];
        Os[row * 68 + c0]           = acc2[nt][0] + bb0;
        Os[row * 68 + c0 + 1]       = acc2[nt][1] + bb1;
        Os[(row + 8) * 68 + c0]     = acc2[nt][2] + bb0;
        Os[(row + 8) * 68 + c0 + 1] = acc2[nt][3] + bb1;
    }
    __syncthreads();

    // ---- store: OUT + residual (re-read from gmem, coalesced) ----
    {
        const float* rsrc = act_in + row0 * DIM + (size_t)n * BLK;
        float* dst = act_out + row0 * DIM + (size_t)n * BLK;
        for (int idx = tid; idx < 2048; idx += 512) {
            int rr = idx >> 4, c4 = idx & 15;
            float4 o = *reinterpret_cast<const float4*>(Os + rr * 68 + c4 * 4);
            float4 a = *reinterpret_cast<const float4*>(rsrc + (size_t)rr * DIM + c4 * 4);
            o.x += a.x; o.y += a.y; o.z += a.z; o.w += a.w;
            *reinterpret_cast<float4*>(dst + (size_t)rr * DIM + c4 * 4) = o;
        }
    }
}

// ============== per-row 64x64 transpose, 2 rows/CTA, float4 both sides ==============
__global__ __launch_bounds__(256)
void transpose64_kernel(const float* __restrict__ in, float* __restrict__ out)
{
    __shared__ float s[2][64 * 65];
    const size_t base = (size_t)blockIdx.x * 2 * DIM;
    const int tid = threadIdx.x;
    for (int i = tid; i < 2048; i += 256) {
        int r = i >> 10, j = i & 1023;
        int a = j >> 4, q = j & 15;
        float4 v = *reinterpret_cast<const float4*>(in + base + (size_t)r * DIM + a * 64 + q * 4);
        float* sp = &s[r][a * 65 + q * 4];
        sp[0] = v.x; sp[1] = v.y; sp[2] = v.z; sp[3] = v.w;
    }
    __syncthreads();
    for (int i = tid; i < 2048; i += 256) {
        int r = i >> 10, j = i & 1023;
        int b = j >> 4, q = j & 15;
        float4 v;
        v.x = s[r][(q * 4 + 0) * 65 + b];
        v.y = s[r][(q * 4 + 1) * 65 + b];
        v.z = s[r][(q * 4 + 2) * 65 + b];
        v.w = s[r][(q * 4 + 3) * 65 + b];
        *reinterpret_cast<float4*>(out + base + (size_t)r * DIM + b * 64 + q * 4) = v;
    }
}

static float* symbol_addr(const void* sym)
{
    void* p = nullptr;
    cudaGetSymbolAddress(&p, sym);
    return (float*)p;
}

extern "C" void kernel_launch(void* const* d_in, const int* in_sizes, int n_in,
                              void* d_out, int out_size)
{
    (void)in_sizes; (void)n_in; (void)out_size;
    const float* x  = (const float*)d_in[0];
    const float* w1 = (const float*)d_in[1];
    const float* b1 = (const float*)d_in[2];
    const float* w2 = (const float*)d_in[3];
    const float* b2 = (const float*)d_in[4];
    float* out = (float*)d_out;

    float* bufA = symbol_addr(g_bufA);
    float* bufB = symbol_addr(g_bufB);

    cudaFuncSetAttribute((const void*)mlp_tc_kernel,
                         cudaFuncAttributeMaxDynamicSharedMemorySize, SMEM_TOTAL);

    prep_weights<<<4096, 512>>>(w1, w2);

    const dim3 grid(BS / 128, NB);
    const size_t ob1 = (size_t)NB * HID, ob2 = (size_t)NB * BLK;

    // layer 0 (gap=1 shuffle = identity)
    mlp_tc_kernel<<<grid, 512, SMEM_TOTAL>>>(x, bufA, 0, b1, b2);
    // gap=64 shuffle: per-row 64x64 transpose
    transpose64_kernel<<<BS / 2, 256>>>(bufA, bufB);
    // layer 1
    mlp_tc_kernel<<<grid, 512, SMEM_TOTAL>>>(bufB, bufA, 1, b1 + ob1, b2 + ob2);
    // inverse shuffle
    transpose64_kernel<<<BS / 2, 256>>>(bufA, out);
}